// round 3
// baseline (speedup 1.0000x reference)
#include <cuda_runtime.h>

// Per-sample 2-layer MLP, 4 samples per CTA, 64 threads per sample.
//   h = relu(x[b,:] @ w1[b,:,:] + b1[b,:])   (D=128 -> H=256)
//   out = h @ w2[b,:,:] + b2[b,:]            (H=256 -> C=64)
// B=4096, grid = 1024 CTAs x 256 threads.
// GEMV1: each thread owns 4 h-columns, accumulates full D=128 in registers
//        (128 float4 LDGs/thread) -> NO cross-thread reduction.
// GEMV2: 64 float4 LDGs/thread, shfl reduce + tiny smem exchange.
// Sample groups are decoupled via named barriers (bar.sync g, 64) -- no
// block-wide sync, so no CTA-wide load-issue lulls at phase boundaries.

#define B_DIM 4096
#define D_DIM 128
#define H_DIM 256
#define C_DIM 64
#define GROUPS 4

__device__ __forceinline__ void group_bar(int g) {
    asm volatile("bar.sync %0, 64;" :: "r"(g) : "memory");
}

__global__ void __launch_bounds__(256, 8) mlp_4samp_kernel(
    const float* __restrict__ x,
    const float* __restrict__ w1,
    const float* __restrict__ b1,
    const float* __restrict__ w2,
    const float* __restrict__ b2,
    float* __restrict__ out)
{
    const int tid = threadIdx.x;
    const int g   = tid >> 6;        // sample group 0..3
    const int t   = tid & 63;        // lane within group
    const int b   = blockIdx.x * GROUPS + g;

    __shared__ float  x_s[GROUPS][D_DIM];
    __shared__ float  h_s[GROUPS][H_DIM];
    __shared__ float4 part[GROUPS][2][16];

    // ---- stage x[b,:]: 64 threads x float2 = 128 floats ----
    reinterpret_cast<float2*>(x_s[g])[t] =
        reinterpret_cast<const float2*>(x + (size_t)b * D_DIM)[t];
    group_bar(g);

    // ========== GEMV1: thread t owns h columns 4t..4t+3, full-D accum ======
    // w1[b] as float4[128][64]; per-d row = 1024B covered by the 64 threads.
    {
        const float4* w1v = reinterpret_cast<const float4*>(
            w1 + (size_t)b * D_DIM * H_DIM);

        float4 acc = make_float4(0.f, 0.f, 0.f, 0.f);
        #pragma unroll 16
        for (int d = 0; d < D_DIM; ++d) {
            const float  xv = x_s[g][d];
            const float4 w  = __ldcs(&w1v[d * (H_DIM / 4) + t]);
            acc.x = fmaf(xv, w.x, acc.x);
            acc.y = fmaf(xv, w.y, acc.y);
            acc.z = fmaf(xv, w.z, acc.z);
            acc.w = fmaf(xv, w.w, acc.w);
        }
        const float4 bb = reinterpret_cast<const float4*>(b1 + (size_t)b * H_DIM)[t];
        float4 h4;
        h4.x = fmaxf(acc.x + bb.x, 0.f);
        h4.y = fmaxf(acc.y + bb.y, 0.f);
        h4.z = fmaxf(acc.z + bb.z, 0.f);
        h4.w = fmaxf(acc.w + bb.w, 0.f);
        reinterpret_cast<float4*>(h_s[g])[t] = h4;
    }
    group_bar(g);

    // ========== GEMV2: out[c] = sum_j h[j] * w2[j, c] ======================
    // w2[b] as float4[256][16]. Thread: (cg = t&15, jq = t>>4 in 0..3),
    // each accumulates 64 j's -> 64 float4 LDGs, coalesced 256B rows.
    {
        const float4* w2v = reinterpret_cast<const float4*>(
            w2 + (size_t)b * H_DIM * C_DIM);
        const int cg    = t & 15;
        const int jbase = (t >> 4) * 64;

        float4 acc = make_float4(0.f, 0.f, 0.f, 0.f);
        #pragma unroll 16
        for (int i = 0; i < 64; ++i) {
            const int j = jbase + i;
            const float  hv = h_s[g][j];
            const float4 w  = __ldcs(&w2v[j * (C_DIM / 4) + cg]);
            acc.x = fmaf(hv, w.x, acc.x);
            acc.y = fmaf(hv, w.y, acc.y);
            acc.z = fmaf(hv, w.z, acc.z);
            acc.w = fmaf(hv, w.w, acc.w);
        }

        // intra-warp reduce: pair (jq, cg) with (jq^1, cg) via shfl_xor(16)
        acc.x += __shfl_xor_sync(0xffffffff, acc.x, 16);
        acc.y += __shfl_xor_sync(0xffffffff, acc.y, 16);
        acc.z += __shfl_xor_sync(0xffffffff, acc.z, 16);
        acc.w += __shfl_xor_sync(0xffffffff, acc.w, 16);

        // lanes 0..15 of each of the group's 2 warps hold warp-level partials
        if ((t & 31) < 16) part[g][t >> 5][cg] = acc;
    }
    group_bar(g);

    if (t < 16) {
        const float4 p0 = part[g][0][t];
        const float4 p1 = part[g][1][t];
        const float4 bb = reinterpret_cast<const float4*>(b2 + (size_t)b * C_DIM)[t];
        float4 o;
        o.x = p0.x + p1.x + bb.x;
        o.y = p0.y + p1.y + bb.y;
        o.z = p0.z + p1.z + bb.z;
        o.w = p0.w + p1.w + bb.w;
        __stcs(reinterpret_cast<float4*>(out + (size_t)b * C_DIM) + t, o);
    }
}

extern "C" void kernel_launch(void* const* d_in, const int* in_sizes, int n_in,
                              void* d_out, int out_size)
{
    const float* x  = (const float*)d_in[0];
    const float* w1 = (const float*)d_in[1];
    const float* b1 = (const float*)d_in[2];
    const float* w2 = (const float*)d_in[3];
    const float* b2 = (const float*)d_in[4];
    float* out = (float*)d_out;

    mlp_4samp_kernel<<<B_DIM / GROUPS, 256>>>(x, w1, b1, w2, b2, out);
}

// round 4
// speedup vs baseline: 1.0180x; 1.0180x over previous
#include <cuda_runtime.h>

// Per-sample 2-layer MLP, 2 samples per CTA (R2 geometry), with the two
// sample halves fully decoupled via per-half named barriers.
//   h = relu(x[b,:] @ w1[b,:,:] + b1[b,:])   (D=128 -> H=256)
//   out = h @ w2[b,:,:] + b2[b,:]            (H=256 -> C=64)
// B=4096, grid = 2048 CTAs x 256 threads; half-block (128 thr) per sample.
// GEMV1: 64 float4 LDGs/thread; GEMV2: 32 float4 LDGs/thread.
// bar.sync s,128 instead of __syncthreads(): half 0 and half 1 drift past
// each other's phase boundaries -> no CTA-wide load-issue lulls.

#define B_DIM 4096
#define D_DIM 128
#define H_DIM 256
#define C_DIM 64

__device__ __forceinline__ void half_bar(int s) {
    asm volatile("bar.sync %0, 128;" :: "r"(s) : "memory");
}

__global__ void __launch_bounds__(256, 6) mlp_2samp_nb_kernel(
    const float* __restrict__ x,
    const float* __restrict__ w1,
    const float* __restrict__ b1,
    const float* __restrict__ w2,
    const float* __restrict__ b2,
    float* __restrict__ out)
{
    const int tid = threadIdx.x;
    const int s   = tid >> 7;        // 0 or 1: which sample this half-block owns
    const int l   = tid & 127;       // lane within half-block
    const int b   = blockIdx.x * 2 + s;

    __shared__ float  x_s[2][D_DIM];
    __shared__ float  h_s[2][H_DIM];
    __shared__ float4 part[2][128];

    // ---- stage x[b,:] ----
    if (l < D_DIM) x_s[s][l] = x[(size_t)b * D_DIM + l];
    half_bar(s);

    // ================= GEMV1: h[j] = sum_d x[d] * w1[d, j] =================
    // w1[b] as float4[128][64]. Thread: (dchunk = l>>6 in 0..1, g = l&63).
    // 64 float4 loads per thread, warp-contiguous 1024B rows.
    {
        const float4* w1v = reinterpret_cast<const float4*>(
            w1 + (size_t)b * D_DIM * H_DIM);
        const int g     = l & 63;
        const int dbase = (l >> 6) * 64;

        float4 acc = make_float4(0.f, 0.f, 0.f, 0.f);
        #pragma unroll
        for (int i = 0; i < 64; ++i) {
            const int d = dbase + i;
            const float  xv = x_s[s][d];
            const float4 w  = __ldcs(&w1v[d * (H_DIM / 4) + g]);
            acc.x = fmaf(xv, w.x, acc.x);
            acc.y = fmaf(xv, w.y, acc.y);
            acc.z = fmaf(xv, w.z, acc.z);
            acc.w = fmaf(xv, w.w, acc.w);
        }
        part[s][l] = acc;
    }
    half_bar(s);

    // reduce 2 partials per column group, add bias, ReLU
    if (l < 64) {
        float4 s0 = part[s][l];
        float4 s1 = part[s][64 + l];
        float4 bb = reinterpret_cast<const float4*>(b1 + (size_t)b * H_DIM)[l];
        float4 h4;
        h4.x = fmaxf(s0.x + s1.x + bb.x, 0.f);
        h4.y = fmaxf(s0.y + s1.y + bb.y, 0.f);
        h4.z = fmaxf(s0.z + s1.z + bb.z, 0.f);
        h4.w = fmaxf(s0.w + s1.w + bb.w, 0.f);
        reinterpret_cast<float4*>(h_s[s])[l] = h4;
    }
    half_bar(s);

    // ================= GEMV2: out[c] = sum_j h[j] * w2[j, c] ===============
    // w2[b] as float4[256][16]. Thread: (jchunk = l>>4 in 0..7, cg = l&15).
    // 32 float4 loads per thread, coalesced 256B row segments.
    {
        const float4* w2v = reinterpret_cast<const float4*>(
            w2 + (size_t)b * H_DIM * C_DIM);
        const int cg    = l & 15;
        const int jbase = (l >> 4) * 32;

        float4 acc = make_float4(0.f, 0.f, 0.f, 0.f);
        #pragma unroll
        for (int i = 0; i < 32; ++i) {
            const int j = jbase + i;
            const float  hv = h_s[s][j];
            const float4 w  = __ldcs(&w2v[j * (C_DIM / 4) + cg]);
            acc.x = fmaf(hv, w.x, acc.x);
            acc.y = fmaf(hv, w.y, acc.y);
            acc.z = fmaf(hv, w.z, acc.z);
            acc.w = fmaf(hv, w.w, acc.w);
        }
        part[s][l] = acc;
    }
    half_bar(s);

    // reduce 8 partials per output group, add bias, streaming store
    if (l < 16) {
        float4 acc = part[s][l];
        #pragma unroll
        for (int k = 1; k < 8; ++k) {
            float4 p = part[s][k * 16 + l];
            acc.x += p.x; acc.y += p.y; acc.z += p.z; acc.w += p.w;
        }
        float4 bb = reinterpret_cast<const float4*>(b2 + (size_t)b * C_DIM)[l];
        acc.x += bb.x; acc.y += bb.y; acc.z += bb.z; acc.w += bb.w;
        __stcs(reinterpret_cast<float4*>(out + (size_t)b * C_DIM) + l, acc);
    }
}

extern "C" void kernel_launch(void* const* d_in, const int* in_sizes, int n_in,
                              void* d_out, int out_size)
{
    const float* x  = (const float*)d_in[0];
    const float* w1 = (const float*)d_in[1];
    const float* b1 = (const float*)d_in[2];
    const float* w2 = (const float*)d_in[3];
    const float* b2 = (const float*)d_in[4];
    float* out = (float*)d_out;

    mlp_2samp_nb_kernel<<<B_DIM / 2, 256>>>(x, w1, b1, w2, b2, out);
}